// round 2
// baseline (speedup 1.0000x reference)
#include <cuda_runtime.h>

// Problem constants (fixed shapes per reference)
#define KROWS 1025
#define F     8192
#define NCHUNK 8
#define ROWS_PER_CHUNK 128   // (KROWS-1)/NCHUNK = 1024/8

// Device scratch (no allocations allowed in kernel_launch)
__device__ float g_partial[NCHUNK * F];
__device__ float g_scale[F];

// Kernel 1: partial column-wise sum of |x| over rows 1..1024, 8 row-chunks,
// float4 vectorized (each thread owns 4 adjacent columns).
__global__ void relu_z_partial_abs(const float* __restrict__ x) {
    int c4    = blockIdx.x * blockDim.x + threadIdx.x;  // 0..F/4-1
    int chunk = blockIdx.y;                             // 0..7
    int r0 = 1 + chunk * ROWS_PER_CHUNK;

    const float4* p = (const float4*)(x + (size_t)r0 * F) + c4;
    float4 s = make_float4(0.f, 0.f, 0.f, 0.f);
    #pragma unroll 4
    for (int r = 0; r < ROWS_PER_CHUNK; ++r) {
        float4 v = *p;
        s.x += fabsf(v.x);
        s.y += fabsf(v.y);
        s.z += fabsf(v.z);
        s.w += fabsf(v.w);
        p += F / 4;
    }
    ((float4*)(g_partial + chunk * F))[c4] = s;
}

// Kernel 2: finalize abssum -> scale; write output row 0 AND the ext diagonal.
// (Ext region must already be zeroed: memset is ordered BEFORE this kernel.)
__global__ void relu_z_finalize(const float* __restrict__ x,
                                const float* __restrict__ lambdas,
                                float* __restrict__ out) {
    int f = blockIdx.x * blockDim.x + threadIdx.x;
    if (f >= F) return;
    float abssum = 0.0f;
    #pragma unroll
    for (int c = 0; c < NCHUNK; ++c) abssum += g_partial[c * F + f];

    float ctr = x[f];                 // x[0][f]
    float l = ctr - abssum;
    float u = ctr + abssum;
    float lam = lambdas[f];

    float pos   = (l > 0.0f) ? 1.0f : 0.0f;
    float cross = ((u > 0.0f) && (l < 0.0f)) ? 1.0f : 0.0f;
    float d     = fmaxf(-l * lam, u * (1.0f - lam));
    float scale = pos + cross * lam;
    float half  = 0.5f * cross * d;

    g_scale[f] = scale;
    out[f] = scale * ctr + half;                      // center row
    out[(size_t)(KROWS + f) * F + f] = half;          // ext diagonal
}

// Kernel 3: out[r] = scale * x[r] for r = 1..KROWS-1, float4 vectorized.
__global__ void relu_z_scale_rows(const float* __restrict__ x,
                                  float* __restrict__ out) {
    int idx = blockIdx.x * blockDim.x + threadIdx.x;
    const int per_row = F / 4;        // 2048
    int r = 1 + idx / per_row;
    int c4 = idx % per_row;
    if (r >= KROWS) return;

    float4 v = ((const float4*)(x + (size_t)r * F))[c4];
    float4 s = ((const float4*)g_scale)[c4];
    float4 o;
    o.x = s.x * v.x;
    o.y = s.y * v.y;
    o.z = s.z * v.z;
    o.w = s.w * v.w;
    ((float4*)(out + (size_t)r * F))[c4] = o;
}

extern "C" void kernel_launch(void* const* d_in, const int* in_sizes, int n_in,
                              void* d_out, int out_size) {
    const float* x       = (const float*)d_in[0];
    const float* lambdas = (const float*)d_in[1];
    float* out           = (float*)d_out;

    // 1) Zero the F x F extension block FIRST (finalize writes the diagonal after).
    cudaMemsetAsync(out + (size_t)KROWS * F, 0, (size_t)F * F * sizeof(float), 0);

    // 2) Partial abs-sums: (F/4/256)=8 col-blocks x 8 row-chunks
    {
        dim3 grid(F / 4 / 256, NCHUNK);
        relu_z_partial_abs<<<grid, 256>>>(x);
    }

    // 3) Finalize scale + center row + ext diagonal
    relu_z_finalize<<<F / 256, 256>>>(x, lambdas, out);

    // 4) Scaled body rows (vectorized; x re-read hits L2)
    {
        int total = (KROWS - 1) * (F / 4);   // 2,097,152
        relu_z_scale_rows<<<(total + 255) / 256, 256>>>(x, out);
    }
}

// round 3
// speedup vs baseline: 1.2072x; 1.2072x over previous
#include <cuda_runtime.h>

// Problem constants (fixed shapes per reference)
#define KROWS 1025
#define F     8192
#define NCHUNK 64
#define ROWS_PER_CHUNK 16   // (KROWS-1)/NCHUNK = 1024/64

// Device scratch (no allocations allowed in kernel_launch)
__device__ float g_partial[NCHUNK * F];   // 2 MB
__device__ float g_scale[F];

// Kernel 1: partial column-wise sum of |x| over rows 1..1024.
// 64 row-chunks x float4 columns -> 512 blocks, 131K threads (latency-hiding).
__global__ void relu_z_partial_abs(const float* __restrict__ x) {
    int c4    = blockIdx.x * blockDim.x + threadIdx.x;  // 0..F/4-1
    int chunk = blockIdx.y;                             // 0..63
    int r0 = 1 + chunk * ROWS_PER_CHUNK;

    const float4* p = (const float4*)(x + (size_t)r0 * F) + c4;
    float4 s = make_float4(0.f, 0.f, 0.f, 0.f);
    #pragma unroll
    for (int r = 0; r < ROWS_PER_CHUNK; ++r) {
        float4 v = p[(size_t)r * (F / 4)];
        s.x += fabsf(v.x);
        s.y += fabsf(v.y);
        s.z += fabsf(v.z);
        s.w += fabsf(v.w);
    }
    ((float4*)(g_partial + chunk * F))[c4] = s;
}

// Kernel 2: finalize abssum -> scale; write output row 0 AND the ext diagonal.
// (Ext region must already be zeroed: memset is ordered BEFORE this kernel.)
__global__ void relu_z_finalize(const float* __restrict__ x,
                                const float* __restrict__ lambdas,
                                float* __restrict__ out) {
    int f = blockIdx.x * blockDim.x + threadIdx.x;
    if (f >= F) return;
    float abssum = 0.0f;
    #pragma unroll
    for (int c = 0; c < NCHUNK; ++c) abssum += g_partial[c * F + f];

    float ctr = x[f];                 // x[0][f]
    float l = ctr - abssum;
    float u = ctr + abssum;
    float lam = lambdas[f];

    float pos   = (l > 0.0f) ? 1.0f : 0.0f;
    float cross = ((u > 0.0f) && (l < 0.0f)) ? 1.0f : 0.0f;
    float d     = fmaxf(-l * lam, u * (1.0f - lam));
    float scale = pos + cross * lam;
    float half  = 0.5f * cross * d;

    g_scale[f] = scale;
    out[f] = scale * ctr + half;                      // center row
    out[(size_t)(KROWS + f) * F + f] = half;          // ext diagonal
}

// Kernel 3: out[r] = scale * x[r] for r = 1..KROWS-1, float4 vectorized.
__global__ void relu_z_scale_rows(const float* __restrict__ x,
                                  float* __restrict__ out) {
    int idx = blockIdx.x * blockDim.x + threadIdx.x;
    const int per_row = F / 4;        // 2048
    int r = 1 + idx / per_row;
    int c4 = idx % per_row;
    if (r >= KROWS) return;

    float4 v = ((const float4*)(x + (size_t)r * F))[c4];
    float4 s = ((const float4*)g_scale)[c4];
    float4 o;
    o.x = s.x * v.x;
    o.y = s.y * v.y;
    o.z = s.z * v.z;
    o.w = s.w * v.w;
    ((float4*)(out + (size_t)r * F))[c4] = o;
}

extern "C" void kernel_launch(void* const* d_in, const int* in_sizes, int n_in,
                              void* d_out, int out_size) {
    const float* x       = (const float*)d_in[0];
    const float* lambdas = (const float*)d_in[1];
    float* out           = (float*)d_out;

    // 1) Zero the F x F extension block FIRST (finalize writes the diagonal after;
    //    also keeps x warm in L2 for scale_rows).
    cudaMemsetAsync(out + (size_t)KROWS * F, 0, (size_t)F * F * sizeof(float), 0);

    // 2) Partial abs-sums: 8 col-blocks x 64 row-chunks = 512 blocks
    {
        dim3 grid(F / 4 / 256, NCHUNK);
        relu_z_partial_abs<<<grid, 256>>>(x);
    }

    // 3) Finalize scale + center row + ext diagonal
    relu_z_finalize<<<F / 256, 256>>>(x, lambdas, out);

    // 4) Scaled body rows (vectorized; x re-read hits L2)
    {
        int total = (KROWS - 1) * (F / 4);   // 2,097,152
        relu_z_scale_rows<<<(total + 255) / 256, 256>>>(x, out);
    }
}